// round 1
// baseline (speedup 1.0000x reference)
#include <cuda_runtime.h>
#include <cuda_bf16.h>
#include <math.h>

// ---------------------------------------------------------------------------
// ESN_2D: state wavefront + XtX/Xty + batched Cholesky solve.  All fp32.
//
// Scratch (device globals, zero runtime allocation):
//   g_S : states, layout S[h][w][b][r]  (r contiguous, 128 per (h,w,b))
//   g_A : per-batch 256x256 normal matrices
//   g_y : per-batch 256 rhs
// ---------------------------------------------------------------------------

#define H_DIM 64
#define W_DIM 64
#define B_DIM 64
#define R_DIM 128
#define D2    256           // 2*R
#define LPOS  (63*63)       // 3969 interior positions

__device__ float g_S[(size_t)H_DIM * W_DIM * B_DIM * R_DIM];   // 128 MB
__device__ float g_A[(size_t)B_DIM * D2 * D2];                 // 16 MB
__device__ float g_y[(size_t)B_DIM * D2];

// ---------------------------------------------------------------------------
// Kernel 1: one anti-diagonal of the ESN recurrence.
// blockIdx.x = cell on diagonal (h = hmin + blockIdx.x, w = d - h)
// blockIdx.y = r-chunk (RCHUNK columns of the 128-wide state)
// 256 threads: 16 b-groups (4 batches each) x 16 r-groups (RCHUNK/16 each).
// ---------------------------------------------------------------------------
template <int RCHUNK>
__global__ __launch_bounds__(256) void esn_diag(
    const float* __restrict__ x,     // input image [B][H][W]
    const float* __restrict__ Win,   // [128]
    const float* __restrict__ W1,    // [128][128] row-major (k, r)
    const float* __restrict__ W2,    // [128][128]
    int d, int hmin)
{
    constexpr int RPT = RCHUNK / 16;

    const int h  = hmin + blockIdx.x;
    const int w  = d - h;
    const int t  = threadIdx.x;
    const int bg = t >> 4;
    const int rg = t & 15;
    const int b0 = bg * 4;
    const int r0 = blockIdx.y * RCHUNK + rg * RPT;

    __shared__ float shL[64][64];   // [k-local][b]  (transposed tiles)
    __shared__ float shA[64][64];

    const float* leftp  = (w > 0) ? (g_S + ((size_t)(h * W_DIM + (w - 1)) * B_DIM) * R_DIM) : nullptr;
    const float* abovep = (h > 0) ? (g_S + ((size_t)((h - 1) * W_DIM + w) * B_DIM) * R_DIM) : nullptr;

    float acc[4][RPT];
#pragma unroll
    for (int i = 0; i < 4; i++)
#pragma unroll
        for (int j = 0; j < RPT; j++) acc[i][j] = 0.0f;

#pragma unroll 1
    for (int kh = 0; kh < 2; kh++) {
        const int k0 = kh * 64;
        __syncthreads();   // protect shared from previous half's readers
        // cooperative transposed load: idx -> (b = idx&63, quad = idx>>6)
        for (int idx = t; idx < 1024; idx += 256) {
            const int b = idx & 63;
            const int q = idx >> 6;           // 0..15
            float4 v = make_float4(0.f, 0.f, 0.f, 0.f);
            float4 u = make_float4(0.f, 0.f, 0.f, 0.f);
            if (leftp)  v = *(const float4*)(leftp  + b * R_DIM + k0 + q * 4);
            if (abovep) u = *(const float4*)(abovep + b * R_DIM + k0 + q * 4);
            shL[q * 4 + 0][b] = v.x; shL[q * 4 + 1][b] = v.y;
            shL[q * 4 + 2][b] = v.z; shL[q * 4 + 3][b] = v.w;
            shA[q * 4 + 0][b] = u.x; shA[q * 4 + 1][b] = u.y;
            shA[q * 4 + 2][b] = u.z; shA[q * 4 + 3][b] = u.w;
        }
        __syncthreads();

#pragma unroll 4
        for (int k = 0; k < 64; k++) {
            const float4 lb = *(const float4*)&shL[k][b0];
            const float4 la = *(const float4*)&shA[k][b0];
            float lbv[4] = {lb.x, lb.y, lb.z, lb.w};
            float lav[4] = {la.x, la.y, la.z, la.w};

            float w1v[RPT], w2v[RPT];
            if constexpr (RPT == 4) {
                const float4 a = *(const float4*)(W1 + (size_t)(k0 + k) * R_DIM + r0);
                const float4 b4 = *(const float4*)(W2 + (size_t)(k0 + k) * R_DIM + r0);
                w1v[0] = a.x;  w1v[1] = a.y;  w1v[2] = a.z;  w1v[3] = a.w;
                w2v[0] = b4.x; w2v[1] = b4.y; w2v[2] = b4.z; w2v[3] = b4.w;
            } else {
#pragma unroll
                for (int j = 0; j < RPT; j++) {
                    w1v[j] = W1[(size_t)(k0 + k) * R_DIM + r0 + j];
                    w2v[j] = W2[(size_t)(k0 + k) * R_DIM + r0 + j];
                }
            }
#pragma unroll
            for (int j = 0; j < RPT; j++)
#pragma unroll
                for (int i = 0; i < 4; i++) {
                    acc[i][j] = fmaf(lbv[i], w1v[j], acc[i][j]);
                    acc[i][j] = fmaf(lav[i], w2v[j], acc[i][j]);
                }
        }
    }

    // epilogue: s = tanh(x * Win + acc)
    float* outp = g_S + ((size_t)(h * W_DIM + w) * B_DIM) * R_DIM;
#pragma unroll
    for (int i = 0; i < 4; i++) {
        const int b = b0 + i;
        const float xv = x[(size_t)b * (H_DIM * W_DIM) + h * W_DIM + w];
#pragma unroll
        for (int j = 0; j < RPT; j++) {
            const int r = r0 + j;
            outp[(size_t)b * R_DIM + r] = tanhf(fmaf(xv, Win[r], acc[i][j]));
        }
    }
}

// ---------------------------------------------------------------------------
// Kernel 2: XtX.  grid = (16 tile-pairs, 64 batches).  CTA computes a 64x64
// tile of A[b] = pre^T pre, 4x4 register tile per thread, k-chunks of 16
// positions staged through shared memory.
// Column tile tc (0..3): tc<2 -> "left" feature S[i+1][j],  tc>=2 -> "above"
// feature S[i][j+1]; column offset within the 128-wide state = (tc&1)*64.
// ---------------------------------------------------------------------------
__global__ __launch_bounds__(256) void xtx_kernel()
{
    const int b  = blockIdx.y;
    const int ti = blockIdx.x >> 2;
    const int tj = blockIdx.x & 3;
    const int t  = threadIdx.x;
    const int di0 = (t & 15) * 4;
    const int dj0 = (t >> 4) * 4;

    __shared__ float sA[16][64];
    __shared__ float sB[16][64];

    float c[4][4] = {};

    const int lr = t >> 4;   // row within chunk 0..15
    const int q  = t & 15;   // float4 quad within 64-wide row

#pragma unroll 1
    for (int l0 = 0; l0 < LPOS; l0 += 16) {
        __syncthreads();
        const int l = l0 + lr;
        float4 va = make_float4(0.f, 0.f, 0.f, 0.f);
        float4 vb = make_float4(0.f, 0.f, 0.f, 0.f);
        if (l < LPOS) {
            const int i = l / 63;
            const int j = l - i * 63;
            {
                const int cell = (ti < 2) ? ((i + 1) * W_DIM + j) : (i * W_DIM + j + 1);
                const int off  = (ti & 1) * 64;
                va = *(const float4*)(g_S + ((size_t)cell * B_DIM + b) * R_DIM + off + q * 4);
            }
            {
                const int cell = (tj < 2) ? ((i + 1) * W_DIM + j) : (i * W_DIM + j + 1);
                const int off  = (tj & 1) * 64;
                vb = *(const float4*)(g_S + ((size_t)cell * B_DIM + b) * R_DIM + off + q * 4);
            }
        }
        *(float4*)&sA[lr][q * 4] = va;
        *(float4*)&sB[lr][q * 4] = vb;
        __syncthreads();

#pragma unroll
        for (int l2 = 0; l2 < 16; l2++) {
            const float4 a  = *(const float4*)&sA[l2][di0];
            const float4 bb = *(const float4*)&sB[l2][dj0];
            float av[4] = {a.x, a.y, a.z, a.w};
            float bv[4] = {bb.x, bb.y, bb.z, bb.w};
#pragma unroll
            for (int ii = 0; ii < 4; ii++)
#pragma unroll
                for (int jj = 0; jj < 4; jj++)
                    c[ii][jj] = fmaf(av[ii], bv[jj], c[ii][jj]);
        }
    }

    const size_t base = (size_t)b * D2 * D2;
#pragma unroll
    for (int ii = 0; ii < 4; ii++) {
        float4 r;
        r.x = c[ii][0]; r.y = c[ii][1]; r.z = c[ii][2]; r.w = c[ii][3];
        *(float4*)(g_A + base + (size_t)(ti * 64 + di0 + ii) * D2 + tj * 64 + dj0) = r;
    }
}

// ---------------------------------------------------------------------------
// Kernel 3: Xty.  grid = 64 batches, 256 threads (one per feature column).
// ---------------------------------------------------------------------------
__global__ __launch_bounds__(256) void xty_kernel(const float* __restrict__ x)
{
    const int b    = blockIdx.x;
    const int dd   = threadIdx.x;
    const int half = dd >> 7;
    const int r    = dd & 127;

    float acc = 0.0f;
#pragma unroll 1
    for (int i = 0; i < 63; i++) {
        const float* tgt_row = x + (size_t)b * (H_DIM * W_DIM) + (i + 1) * W_DIM + 1;
#pragma unroll 4
        for (int j = 0; j < 63; j++) {
            const int cell = (half == 0) ? ((i + 1) * W_DIM + j) : (i * W_DIM + j + 1);
            const float v = g_S[((size_t)cell * B_DIM + b) * R_DIM + r];
            acc = fmaf(v, tgt_row[j], acc);
        }
    }
    g_y[(size_t)b * D2 + dd] = acc;
}

// ---------------------------------------------------------------------------
// Kernel 4: per-batch Cholesky solve of (XtX + 0.9 I) w = Xty.
// Packed lower triangle in dynamic shared memory (256*257/2 floats).
// Column-parallel right-looking Cholesky, then two triangular solves.
// ---------------------------------------------------------------------------
#define PK_ELEMS (D2 * (D2 + 1) / 2)          // 32896
#define SOLVE_SMEM ((PK_ELEMS + 4 * D2) * 4)  // P + col + dg + zz + xs

__global__ __launch_bounds__(256) void solve_kernel(float* __restrict__ out)
{
    extern __shared__ float sm[];
    float* P   = sm;
    float* col = sm + PK_ELEMS;
    float* dg  = col + D2;
    float* zz  = dg + D2;
    float* xs  = zz + D2;

    const int b = blockIdx.x;
    const int t = threadIdx.x;
    const float* A = g_A + (size_t)b * D2 * D2;

    // load packed lower triangle, add ridge on diagonal
#pragma unroll 1
    for (int i = 0; i < D2; i++) {
        const int base = i * (i + 1) / 2;
        for (int j = t; j <= i; j += 256)
            P[base + j] = A[(size_t)i * D2 + j] + ((j == i) ? 0.9f : 0.0f);
    }
    zz[t] = g_y[(size_t)b * D2 + t];
    __syncthreads();

    // right-looking Cholesky (lower).  Diagonal kept in dg[] (P diag untouched).
#pragma unroll 1
    for (int k = 0; k < D2; k++) {
        const int bk = k * (k + 1) / 2;
        const float dkk = sqrtf(P[bk + k]);     // all threads read; nobody writes it
        const float rinv = 1.0f / dkk;
        if (t == k) { dg[k] = dkk; col[k] = dkk; }
        if (t > k) {
            const int Tt = t * (t + 1) / 2;
            const float lik = P[Tt + k] * rinv;
            P[Tt + k] = lik;
            col[t] = lik;
        }
        __syncthreads();
        if (t > k) {
            const float cj = col[t];
            int Ti = t * (t + 1) / 2;
#pragma unroll 4
            for (int i = t; i < D2; i++) {
                P[Ti + t] -= col[i] * cj;
                Ti += i + 1;
            }
        }
        __syncthreads();
    }

    // forward solve L z = y   (z stored into xs)
#pragma unroll 1
    for (int k = 0; k < D2; k++) {
        __syncthreads();
        const float xk = zz[k] / dg[k];
        if (t == k) xs[k] = xk;
        if (t > k)  zz[t] -= P[t * (t + 1) / 2 + k] * xk;
    }
    __syncthreads();

    // backward solve L^T w = z
#pragma unroll 1
    for (int k = D2 - 1; k >= 0; k--) {
        __syncthreads();
        const float wk = xs[k] / dg[k];
        if (t == k) out[(size_t)b * D2 + k] = wk;
        if (t < k)  xs[t] -= P[k * (k + 1) / 2 + t] * wk;
    }
}

// ---------------------------------------------------------------------------
// kernel_launch
// ---------------------------------------------------------------------------
extern "C" void kernel_launch(void* const* d_in, const int* in_sizes, int n_in,
                              void* d_out, int out_size)
{
    const float* x   = (const float*)d_in[0];   // input_image  (64,64,64)
    const float* Win = (const float*)d_in[1];   // W_in   (1,128)
    const float* W1  = (const float*)d_in[2];   // W_res_1 (128,128)
    const float* W2  = (const float*)d_in[3];   // W_res_2 (128,128)
    float* out = (float*)d_out;                 // (64, 256)
    (void)in_sizes; (void)n_in; (void)out_size;

    cudaFuncSetAttribute(solve_kernel,
                         cudaFuncAttributeMaxDynamicSharedMemorySize, SOLVE_SMEM);

    // wavefront over anti-diagonals
    for (int d = 0; d < H_DIM + W_DIM - 1; d++) {
        const int hmin = (d - (W_DIM - 1) > 0) ? (d - (W_DIM - 1)) : 0;
        const int hmax = (d < H_DIM - 1) ? d : (H_DIM - 1);
        const int n = hmax - hmin + 1;
        if (n <= 18) {
            dim3 grid(n, 8);
            esn_diag<16><<<grid, 256>>>(x, Win, W1, W2, d, hmin);
        } else if (n <= 37) {
            dim3 grid(n, 4);
            esn_diag<32><<<grid, 256>>>(x, Win, W1, W2, d, hmin);
        } else {
            dim3 grid(n, 2);
            esn_diag<64><<<grid, 256>>>(x, Win, W1, W2, d, hmin);
        }
    }

    xtx_kernel<<<dim3(16, B_DIM), 256>>>();
    xty_kernel<<<B_DIM, 256>>>(x);
    solve_kernel<<<B_DIM, 256, SOLVE_SMEM>>>(out);
}

// round 2
// speedup vs baseline: 1.0281x; 1.0281x over previous
#include <cuda_runtime.h>
#include <math.h>

// ---------------------------------------------------------------------------
// ESN_2D round 2: persistent wavefront kernel (grid barrier, smem-resident
// weights, packed f32x2 FMA) + symmetric f32x2 XtX + Xty + Cholesky solve.
// ---------------------------------------------------------------------------

#define H_DIM 64
#define W_DIM 64
#define B_DIM 64
#define R_DIM 128
#define D2    256
#define LPOS  (63*63)
#define NCTA  128

// scratch (device globals; no runtime allocation)
__device__ float g_S [(size_t)H_DIM * W_DIM * B_DIM * R_DIM];  // [cell][b][r]
__device__ float g_St[(size_t)H_DIM * W_DIM * R_DIM * B_DIM];  // [cell][r][b]
__device__ float g_A [(size_t)B_DIM * D2 * D2];
__device__ float g_y [(size_t)B_DIM * D2];

__device__ volatile unsigned g_gen;   // barrier generation (monotonic)
__device__ unsigned          g_cnt;   // barrier arrival counter (returns to 0)

// ---------------------------------------------------------------------------
// packed fp32x2 helpers (sm_100a)
// ---------------------------------------------------------------------------
__device__ __forceinline__ unsigned long long ffma2(unsigned long long a,
                                                    unsigned long long b,
                                                    unsigned long long c)
{
    unsigned long long d;
    asm("fma.rn.f32x2 %0, %1, %2, %3;" : "=l"(d) : "l"(a), "l"(b), "l"(c));
    return d;
}
__device__ __forceinline__ float2 unpack2(unsigned long long v)
{
    float2 r;
    asm("mov.b64 {%0, %1}, %2;" : "=f"(r.x), "=f"(r.y) : "l"(v));
    return r;
}

// ---------------------------------------------------------------------------
// grid barrier (sense-reversal via generation counter; safe across graph
// replays: g_cnt returns to 0, g_gen is compared relatively)
// ---------------------------------------------------------------------------
__device__ __forceinline__ void grid_barrier()
{
    __threadfence();
    __syncthreads();
    if (threadIdx.x == 0) {
        unsigned gen = g_gen;
        if (atomicAdd(&g_cnt, 1u) == NCTA - 1) {
            g_cnt = 0;
            __threadfence();
            g_gen = gen + 1;
        } else {
            while (g_gen == gen) { __nanosleep(64); }
        }
    }
    __syncthreads();
    __threadfence();
}

// ---------------------------------------------------------------------------
// per-item compute: 64 (or 32) batches x 64 r, k over present halves.
// JR = r-values per thread (4 -> 64 batches, 2 -> 32 batches).
// ss : staged states  [k 0..255][b_local]  (float, b contiguous)
// sw2: duplicated weights [k][r_local] as (w,w) float2
// st : [64][68] transpose staging for the g_St writeback (aliases ss)
// ---------------------------------------------------------------------------
template <int JR>
__device__ __forceinline__ void item_compute(
    const float* __restrict__ ss, const float2* __restrict__ sw2, float* st,
    const float* __restrict__ x, const float* __restrict__ Win,
    int klo, int khi, int h, int w, int bbase, int r0g, int t)
{
    const int bg  = (JR == 4) ? (t >> 4) : (t >> 5);
    const int rg  = (JR == 4) ? (t & 15) : (t & 31);
    const int b0l = bg << 2;            // 4 local batches (2 pairs)
    const int rl0 = rg * JR;            // JR local r columns

    unsigned long long acc[2][JR];
#pragma unroll
    for (int p = 0; p < 2; p++)
#pragma unroll
        for (int j = 0; j < JR; j++) acc[p][j] = 0ull;

#pragma unroll 4
    for (int k = klo; k < khi; k++) {
        const ulonglong2 sv = *(const ulonglong2*)(ss + (k << 6) + b0l);
        if constexpr (JR == 4) {
            const ulonglong2 w01 = *(const ulonglong2*)(sw2 + (k << 6) + rl0);
            const ulonglong2 w23 = *(const ulonglong2*)(sw2 + (k << 6) + rl0 + 2);
            acc[0][0] = ffma2(sv.x, w01.x, acc[0][0]);
            acc[1][0] = ffma2(sv.y, w01.x, acc[1][0]);
            acc[0][1] = ffma2(sv.x, w01.y, acc[0][1]);
            acc[1][1] = ffma2(sv.y, w01.y, acc[1][1]);
            acc[0][2] = ffma2(sv.x, w23.x, acc[0][2]);
            acc[1][2] = ffma2(sv.y, w23.x, acc[1][2]);
            acc[0][3] = ffma2(sv.x, w23.y, acc[0][3]);
            acc[1][3] = ffma2(sv.y, w23.y, acc[1][3]);
        } else {
            const ulonglong2 w01 = *(const ulonglong2*)(sw2 + (k << 6) + rl0);
            acc[0][0] = ffma2(sv.x, w01.x, acc[0][0]);
            acc[1][0] = ffma2(sv.y, w01.x, acc[1][0]);
            acc[0][1] = ffma2(sv.x, w01.y, acc[0][1]);
            acc[1][1] = ffma2(sv.y, w01.y, acc[1][1]);
        }
    }

    float wv[JR];
#pragma unroll
    for (int j = 0; j < JR; j++) wv[j] = Win[r0g + rl0 + j];

    __syncthreads();   // everyone done reading ss before st (alias) writes

    float* gS = g_S + ((size_t)(h * W_DIM + w) << 13);
    const int xoff = (h << 6) + w;

#pragma unroll
    for (int p = 0; p < 2; p++) {
        const int blp = b0l + 2 * p;
        const int bA  = bbase + blp;
        const float x0 = x[((size_t)bA << 12) + xoff];
        const float x1 = x[((size_t)(bA + 1) << 12) + xoff];
        float o0[JR], o1[JR];
#pragma unroll
        for (int j = 0; j < JR; j++) {
            const float2 v = unpack2(acc[p][j]);
            o0[j] = tanhf(fmaf(x0, wv[j], v.x));
            o1[j] = tanhf(fmaf(x1, wv[j], v.y));
        }
        if constexpr (JR == 4) {
            *(float4*)(gS + ((size_t)bA << 7) + r0g + rl0) =
                make_float4(o0[0], o0[1], o0[2], o0[3]);
            *(float4*)(gS + ((size_t)(bA + 1) << 7) + r0g + rl0) =
                make_float4(o1[0], o1[1], o1[2], o1[3]);
        } else {
            *(float2*)(gS + ((size_t)bA << 7) + r0g + rl0) = make_float2(o0[0], o0[1]);
            *(float2*)(gS + ((size_t)(bA + 1) << 7) + r0g + rl0) = make_float2(o1[0], o1[1]);
        }
#pragma unroll
        for (int j = 0; j < JR; j++)
            *(float2*)&st[(rl0 + j) * 68 + blp] = make_float2(o0[j], o1[j]);
    }
}

// ---------------------------------------------------------------------------
// persistent ESN wavefront kernel.  grid = 128 CTAs x 256 threads.
// CTA parity selects the r-half it owns (weights cached for that half).
// ---------------------------------------------------------------------------
__global__ __launch_bounds__(256, 1) void esn_persist(
    const float* __restrict__ x, const float* __restrict__ Win,
    const float* __restrict__ W1, const float* __restrict__ W2)
{
    extern __shared__ float sm[];
    float2* sw2 = (float2*)sm;          // [256][64] duplicated weights (128KB)
    float*  ss  = sm + 32768;           // [256][64] staged states (64KB)
    float*  st  = sm + 32768;           // [64][68] alias, used post-compute

    const int t = threadIdx.x;
    const int parity = blockIdx.x & 1;
    const int r0g = parity << 6;

    // one-time weight load (duplicated pairs)
    for (int u = t; u < 16384; u += 256) {
        const int k = u >> 6, rl = u & 63;
        const float v = (k < 128) ? W1[k * R_DIM + r0g + rl]
                                  : W2[(k - 128) * R_DIM + r0g + rl];
        sw2[u] = make_float2(v, v);
    }
    __syncthreads();

    for (int d = 0; d < H_DIM + W_DIM - 1; d++) {
        const int hmin = (d > W_DIM - 1) ? d - (W_DIM - 1) : 0;
        const int hmax = (d < H_DIM - 1) ? d : H_DIM - 1;
        const int n = hmax - hmin + 1;
        const bool modeB = (n <= 32);
        const int i = blockIdx.x >> 1;
        const int nitems = modeB ? 2 * n : n;

        if (i < nitems) {
            const int cell_i = modeB ? (i >> 1) : i;
            const int bbase  = modeB ? ((i & 1) << 5) : 0;
            const int nb     = modeB ? 32 : 64;
            const int h = hmin + cell_i;
            const int w = d - h;
            const int qs = modeB ? 3 : 4;      // float4's per k-row
            const int nq = 1 << qs;

            if (w > 0) {
                const float* src = g_St + ((size_t)(h * W_DIM + w - 1) << 13);
                for (int u = t; u < (128 << qs); u += 256) {
                    const int k = u >> qs, bq = u & (nq - 1);
                    *(float4*)&ss[(k << 6) + (bq << 2)] =
                        *(const float4*)(src + ((size_t)k << 6) + bbase + (bq << 2));
                }
            }
            if (h > 0) {
                const float* src = g_St + ((size_t)((h - 1) * W_DIM + w) << 13);
                for (int u = t; u < (128 << qs); u += 256) {
                    const int k = u >> qs, bq = u & (nq - 1);
                    *(float4*)&ss[((128 + k) << 6) + (bq << 2)] =
                        *(const float4*)(src + ((size_t)k << 6) + bbase + (bq << 2));
                }
            }
            __syncthreads();

            const int klo = (w > 0) ? 0 : 128;
            const int khi = (h > 0) ? 256 : 128;
            if (modeB) item_compute<2>(ss, sw2, st, x, Win, klo, khi, h, w, bbase, r0g, t);
            else       item_compute<4>(ss, sw2, st, x, Win, klo, khi, h, w, bbase, r0g, t);

            __syncthreads();   // st fully written
            float* gT = g_St + ((size_t)(h * W_DIM + w) << 13);
            const int qs2 = modeB ? 3 : 4;
            for (int u = t; u < (64 << qs2); u += 256) {
                const int row = u >> qs2, q = u & ((1 << qs2) - 1);
                *(float4*)(gT + ((size_t)(r0g + row) << 6) + bbase + (q << 2)) =
                    *(const float4*)&st[row * 68 + (q << 2)];
            }
            (void)nb;
        }
        grid_barrier();
    }
}

// ---------------------------------------------------------------------------
// XtX: symmetric, f32x2.  grid = (10 tile-pairs, 64 batches).
// CTA computes 64x64 tile (ti,tj), tj>=ti, mirrors on write.
// ---------------------------------------------------------------------------
__global__ __launch_bounds__(256) void xtx_kernel()
{
    const int b = blockIdx.y;
    const int p = blockIdx.x;
    const int ti = (p < 4) ? 0 : (p < 7) ? 1 : (p < 9) ? 2 : 3;
    const int tbase = (ti == 0) ? 0 : (ti == 1) ? 4 : (ti == 2) ? 7 : 9;
    const int tj = ti + (p - tbase);

    const int t = threadIdx.x;
    const int di0 = (t & 15) << 2;
    const int dj0 = (t >> 4) << 2;

    __shared__ float  sA [16][64];
    __shared__ float2 sBd[16][64];   // duplicated pairs

    unsigned long long acc[2][4];
#pragma unroll
    for (int pp = 0; pp < 2; pp++)
#pragma unroll
        for (int j = 0; j < 4; j++) acc[pp][j] = 0ull;

    const int lr = t >> 4;
    const int q  = t & 15;

#pragma unroll 1
    for (int l0 = 0; l0 < LPOS; l0 += 16) {
        __syncthreads();
        const int l = l0 + lr;
        float4 va = make_float4(0.f, 0.f, 0.f, 0.f);
        float4 vb = make_float4(0.f, 0.f, 0.f, 0.f);
        if (l < LPOS) {
            const int i = l / 63;
            const int j = l - i * 63;
            {
                const int cell = (ti < 2) ? ((i + 1) * W_DIM + j) : (i * W_DIM + j + 1);
                const int off  = (ti & 1) << 6;
                va = *(const float4*)(g_S + (((size_t)cell << 6) + b) * R_DIM + off + (q << 2));
            }
            {
                const int cell = (tj < 2) ? ((i + 1) * W_DIM + j) : (i * W_DIM + j + 1);
                const int off  = (tj & 1) << 6;
                vb = *(const float4*)(g_S + (((size_t)cell << 6) + b) * R_DIM + off + (q << 2));
            }
        }
        *(float4*)&sA[lr][q << 2] = va;
        *(float4*)&sBd[lr][(q << 2)]     = *(float4*)&(float2[2]){ make_float2(vb.x, vb.x), make_float2(vb.y, vb.y) };
        *(float4*)&sBd[lr][(q << 2) + 2] = *(float4*)&(float2[2]){ make_float2(vb.z, vb.z), make_float2(vb.w, vb.w) };
        __syncthreads();

#pragma unroll
        for (int l2 = 0; l2 < 16; l2++) {
            const ulonglong2 av  = *(const ulonglong2*)&sA[l2][di0];
            const ulonglong2 b01 = *(const ulonglong2*)&sBd[l2][dj0];
            const ulonglong2 b23 = *(const ulonglong2*)&sBd[l2][dj0 + 2];
            acc[0][0] = ffma2(av.x, b01.x, acc[0][0]);
            acc[1][0] = ffma2(av.y, b01.x, acc[1][0]);
            acc[0][1] = ffma2(av.x, b01.y, acc[0][1]);
            acc[1][1] = ffma2(av.y, b01.y, acc[1][1]);
            acc[0][2] = ffma2(av.x, b23.x, acc[0][2]);
            acc[1][2] = ffma2(av.y, b23.x, acc[1][2]);
            acc[0][3] = ffma2(av.x, b23.y, acc[0][3]);
            acc[1][3] = ffma2(av.y, b23.y, acc[1][3]);
        }
    }

    float c[4][4];
#pragma unroll
    for (int pp = 0; pp < 2; pp++)
#pragma unroll
        for (int j = 0; j < 4; j++) {
            const float2 v = unpack2(acc[pp][j]);
            c[2 * pp][j] = v.x;
            c[2 * pp + 1][j] = v.y;
        }

    const size_t base = (size_t)b * D2 * D2;
#pragma unroll
    for (int ii = 0; ii < 4; ii++)
        *(float4*)(g_A + base + (size_t)(ti * 64 + di0 + ii) * D2 + tj * 64 + dj0) =
            make_float4(c[ii][0], c[ii][1], c[ii][2], c[ii][3]);
    if (ti != tj) {
#pragma unroll
        for (int jj = 0; jj < 4; jj++)
            *(float4*)(g_A + base + (size_t)(tj * 64 + dj0 + jj) * D2 + ti * 64 + di0) =
                make_float4(c[0][jj], c[1][jj], c[2][jj], c[3][jj]);
    }
}

// ---------------------------------------------------------------------------
// Xty
// ---------------------------------------------------------------------------
__global__ __launch_bounds__(256) void xty_kernel(const float* __restrict__ x)
{
    const int b    = blockIdx.x;
    const int dd   = threadIdx.x;
    const int half = dd >> 7;
    const int r    = dd & 127;

    float acc = 0.0f;
#pragma unroll 1
    for (int i = 0; i < 63; i++) {
        const float* tgt_row = x + (size_t)b * (H_DIM * W_DIM) + (i + 1) * W_DIM + 1;
#pragma unroll 4
        for (int j = 0; j < 63; j++) {
            const int cell = (half == 0) ? ((i + 1) * W_DIM + j) : (i * W_DIM + j + 1);
            const float v = g_S[((size_t)cell * B_DIM + b) * R_DIM + r];
            acc = fmaf(v, tgt_row[j], acc);
        }
    }
    g_y[(size_t)b * D2 + dd] = acc;
}

// ---------------------------------------------------------------------------
// Cholesky solve (unchanged from R1)
// ---------------------------------------------------------------------------
#define PK_ELEMS (D2 * (D2 + 1) / 2)
#define SOLVE_SMEM ((PK_ELEMS + 4 * D2) * 4)

__global__ __launch_bounds__(256) void solve_kernel(float* __restrict__ out)
{
    extern __shared__ float smref[];
    float* P   = smref;
    float* col = smref + PK_ELEMS;
    float* dg  = col + D2;
    float* zz  = dg + D2;
    float* xs  = zz + D2;

    const int b = blockIdx.x;
    const int t = threadIdx.x;
    const float* A = g_A + (size_t)b * D2 * D2;

#pragma unroll 1
    for (int i = 0; i < D2; i++) {
        const int base = i * (i + 1) / 2;
        for (int j = t; j <= i; j += 256)
            P[base + j] = A[(size_t)i * D2 + j] + ((j == i) ? 0.9f : 0.0f);
    }
    zz[t] = g_y[(size_t)b * D2 + t];
    __syncthreads();

#pragma unroll 1
    for (int k = 0; k < D2; k++) {
        const int bk = k * (k + 1) / 2;
        const float dkk = sqrtf(P[bk + k]);
        const float rinv = 1.0f / dkk;
        if (t == k) { dg[k] = dkk; col[k] = dkk; }
        if (t > k) {
            const int Tt = t * (t + 1) / 2;
            const float lik = P[Tt + k] * rinv;
            P[Tt + k] = lik;
            col[t] = lik;
        }
        __syncthreads();
        if (t > k) {
            const float cj = col[t];
            int Ti = t * (t + 1) / 2;
#pragma unroll 4
            for (int i = t; i < D2; i++) {
                P[Ti + t] -= col[i] * cj;
                Ti += i + 1;
            }
        }
        __syncthreads();
    }

#pragma unroll 1
    for (int k = 0; k < D2; k++) {
        __syncthreads();
        const float xk = zz[k] / dg[k];
        if (t == k) xs[k] = xk;
        if (t > k)  zz[t] -= P[t * (t + 1) / 2 + k] * xk;
    }
    __syncthreads();

#pragma unroll 1
    for (int k = D2 - 1; k >= 0; k--) {
        __syncthreads();
        const float wk = xs[k] / dg[k];
        if (t == k) out[(size_t)b * D2 + k] = wk;
        if (t < k)  xs[t] -= P[k * (k + 1) / 2 + t] * wk;
    }
}

// ---------------------------------------------------------------------------
// kernel_launch
// ---------------------------------------------------------------------------
#define ESN_SMEM (131072 + 65536)

extern "C" void kernel_launch(void* const* d_in, const int* in_sizes, int n_in,
                              void* d_out, int out_size)
{
    const float* x   = (const float*)d_in[0];
    const float* Win = (const float*)d_in[1];
    const float* W1  = (const float*)d_in[2];
    const float* W2  = (const float*)d_in[3];
    float* out = (float*)d_out;
    (void)in_sizes; (void)n_in; (void)out_size;

    static int attr_done = 0;
    if (!attr_done) {
        cudaFuncSetAttribute(esn_persist,
                             cudaFuncAttributeMaxDynamicSharedMemorySize, ESN_SMEM);
        cudaFuncSetAttribute(solve_kernel,
                             cudaFuncAttributeMaxDynamicSharedMemorySize, SOLVE_SMEM);
        attr_done = 1;
    }

    esn_persist<<<NCTA, 256, ESN_SMEM>>>(x, Win, W1, W2);
    xtx_kernel<<<dim3(10, B_DIM), 256>>>();
    xty_kernel<<<B_DIM, 256>>>(x);
    solve_kernel<<<B_DIM, 256, SOLVE_SMEM>>>(out);
}